// round 2
// baseline (speedup 1.0000x reference)
#include <cuda_runtime.h>

// Problem constants
#define B_   8
#define H_   64
#define W_   64
#define C_   256
#define RED_ 64
#define KK_  9
#define G_   16
#define GC_  16
#define E_   144          // KK_*G_
#define NPIX (B_*H_*W_)   // 32768

// Scratch (allowed: __device__ globals, no allocation)
__device__ __align__(16) float g_weff[C_ * E_];   // 256x144
__device__ __align__(16) float g_beff[E_];
__device__ __align__(16) float g_wgt[(size_t)NPIX * E_]; // 32768x144

// ---------------------------------------------------------------------------
// Kernel 0: Weff = W1 @ W2  (256x64 @ 64x144), beff = b1 @ W2 + b2
// grid = 257 blocks x 144 threads. block c<256: row c of Weff. block 256: beff.
// ---------------------------------------------------------------------------
__global__ void weff_kernel(const float* __restrict__ W1,
                            const float* __restrict__ b1,
                            const float* __restrict__ W2,
                            const float* __restrict__ b2)
{
    __shared__ float row[RED_];
    int c = blockIdx.x;
    int e = threadIdx.x;          // 0..143
    if (c < C_) {
        if (e < RED_) row[e] = W1[c * RED_ + e];
        __syncthreads();
        float acc = 0.f;
        #pragma unroll 8
        for (int d = 0; d < RED_; ++d)
            acc += row[d] * W2[d * E_ + e];
        g_weff[c * E_ + e] = acc;
    } else {
        if (e < RED_) row[e] = b1[e];
        __syncthreads();
        float acc = b2[e];
        #pragma unroll 8
        for (int d = 0; d < RED_; ++d)
            acc += row[d] * W2[d * E_ + e];
        g_beff[e] = acc;
    }
}

// ---------------------------------------------------------------------------
// Kernel 1: wgt[p][e] = x[p][:] @ Weff[:, e] + beff[e]
// GEMM M=32768, N=144, K=256.  Block: Mtile=64 pixels, full N=144.
// 256 threads: tm = tid&63 (pixel), tn = tid>>6 (0..3, 36 n-values each).
// Per k-step: 1 LDS (a, conflict-free) + 9 broadcast LDG.128 (Weff, L1-hot)
// + 36 FFMA -> FMA-pipe bound.
// ---------------------------------------------------------------------------
__global__ __launch_bounds__(256) void wgt_gemm_kernel(const float* __restrict__ x)
{
    __shared__ float xs[32][65];   // [kchunk][m], padded: conflict-free STS & LDS
    const int tid = threadIdx.x;
    const int tm  = tid & 63;
    const int tn  = tid >> 6;      // 0..3
    const int nb  = tn * 36;
    const int pm0 = blockIdx.x * 64;

    float4 acc[9];
    {
        const float4* bp = reinterpret_cast<const float4*>(g_beff + nb);
        #pragma unroll
        for (int j = 0; j < 9; ++j) acc[j] = bp[j];
    }

    for (int kc = 0; kc < C_; kc += 32) {
        #pragma unroll
        for (int i = 0; i < 8; ++i) {
            int idx = tid + i * 256;
            int m = idx >> 5;
            int k = idx & 31;
            xs[k][m] = x[(size_t)(pm0 + m) * C_ + kc + k];
        }
        __syncthreads();
        #pragma unroll 4
        for (int k = 0; k < 32; ++k) {
            float a = xs[k][tm];
            const float4* wrow =
                reinterpret_cast<const float4*>(g_weff + (kc + k) * E_ + nb);
            #pragma unroll
            for (int j = 0; j < 9; ++j) {
                float4 bv = __ldg(&wrow[j]);
                acc[j].x += a * bv.x;
                acc[j].y += a * bv.y;
                acc[j].z += a * bv.z;
                acc[j].w += a * bv.w;
            }
        }
        __syncthreads();
    }

    float4* op = reinterpret_cast<float4*>(g_wgt + (size_t)(pm0 + tm) * E_ + nb);
    #pragma unroll
    for (int j = 0; j < 9; ++j) op[j] = acc[j];
}

// ---------------------------------------------------------------------------
// Kernel 2: involution apply with scrambled (k,ch) -> (o,e) mapping.
// out[p][o] = sum_{k'=0..8} wgt[p][g*9+k'] * x[neigh(k)][ch],
//   f = g*144 + (o&15)*9 + k',  ch = f&255, k = f>>8  (g = o>>4).
// Block: 8-pixel w-strip. smem: 3x10x256 halo tile + wgt tile + u16 offset table.
// warp = one pixel, lanes = output channels (o = 32*i + lane).
// xs bank index = ch mod 32; ch strides by 9 across lanes -> conflict-free.
// ---------------------------------------------------------------------------
__global__ __launch_bounds__(256) void invo_kernel(const float* __restrict__ x,
                                                   float* __restrict__ out)
{
    __shared__ float xs[3][10][C_];          // 30720 B
    __shared__ float wgts[8][E_];            //  4608 B
    __shared__ unsigned short T[KK_][256];   //  4608 B

    const int tid = threadIdx.x;
    const int w0  = blockIdx.x * 8;
    const int h   = blockIdx.y;
    const int b   = blockIdx.z;

    // --- load halo tile (zero-padded SAME) ---
    #pragma unroll
    for (int it = 0; it < 30; ++it) {
        int r  = it / 10;
        int cc = it - r * 10;
        int hh = h - 1 + r;
        int ww = w0 - 1 + cc;
        float v = 0.f;
        if (hh >= 0 && hh < H_ && ww >= 0 && ww < W_)
            v = x[(((size_t)b * H_ + hh) * W_ + ww) * C_ + tid];
        xs[r][cc][tid] = v;
    }

    // --- load wgt tile ---
    const int p0 = (b * H_ + h) * W_ + w0;
    #pragma unroll
    for (int it = 0; it < 5; ++it) {
        int idx = tid + it * 256;
        if (idx < 8 * E_) {
            int pp = idx / E_;
            int e  = idx - pp * E_;
            wgts[pp][e] = g_wgt[(size_t)(p0 + pp) * E_ + e];
        }
    }

    // --- build offset table: T[k'][o] = (di*10 + dj)*256 + ch ---
    {
        int o   = tid;
        int g   = o >> 4;
        int gc2 = o & 15;
        int fb  = g * 144 + gc2 * 9;
        #pragma unroll
        for (int kp = 0; kp < KK_; ++kp) {
            int f  = fb + kp;
            int ch = f & 255;
            int k  = f >> 8;          // 0..8
            int di = k / 3;
            int dj = k - di * 3;
            T[kp][o] = (unsigned short)(((di * 10 + dj) << 8) + ch);
        }
    }
    __syncthreads();

    // --- compute ---
    const int p = tid >> 5;           // pixel in strip (warp id)
    const int l = tid & 31;           // lane -> o subset
    const float* xsp  = &xs[0][0][0] + p * C_;   // shift col by pixel index
    const float* wrow = &wgts[p][0];

    float acc[8];
    #pragma unroll
    for (int i = 0; i < 8; ++i) {
        int o = (i << 5) + l;
        int g = o >> 4;
        const int wb = g * 9;
        float a = 0.f;
        #pragma unroll
        for (int kp = 0; kp < KK_; ++kp) {
            int t = T[kp][o];
            a += wrow[wb + kp] * xsp[t];
        }
        acc[i] = a;
    }

    float* op = out + (size_t)(p0 + p) * C_ + l;
    #pragma unroll
    for (int i = 0; i < 8; ++i) op[i * 32] = acc[i];
}

// ---------------------------------------------------------------------------
extern "C" void kernel_launch(void* const* d_in, const int* in_sizes, int n_in,
                              void* d_out, int out_size)
{
    const float* x  = (const float*)d_in[0];
    const float* W1 = (const float*)d_in[1];
    const float* b1 = (const float*)d_in[2];
    const float* W2 = (const float*)d_in[3];
    const float* b2 = (const float*)d_in[4];
    float* out = (float*)d_out;

    weff_kernel<<<257, 144>>>(W1, b1, W2, b2);
    wgt_gemm_kernel<<<NPIX / 64, 256>>>(x);
    invo_kernel<<<dim3(W_ / 8, H_, B_), 256>>>(x, out);
}

// round 5
// speedup vs baseline: 3.2063x; 3.2063x over previous
#include <cuda_runtime.h>
#include <cstdint>

// Problem constants
#define B_   8
#define H_   64
#define W_   64
#define C_   256
#define RED_ 64
#define KK_  9
#define G_   16
#define GC_  16
#define E_   144          // KK_*G_
#define NPIX (B_*H_*W_)   // 32768

// Scratch (__device__ globals; no allocation)
// B in mma-fragment order: [kstep(32)][ntile(18)][lane(32)][2]  (b0,b1)
__device__ __align__(16) float g_weffB[32 * 18 * 32 * 2];     // 147456 B
__device__ __align__(16) float g_beff[E_];
__device__ __align__(16) float g_wgt[(size_t)NPIX * E_];      // 32768x144

// ---------------------------------------------------------------------------
// Kernel 0: Weff = W1@W2 scattered into mma fragment order; beff = b1@W2 + b2
// For element (c,e): kstep=c>>3, r=c&7 -> klane=r&3, jbit=r>>2;
// ntile=e>>3, lane=(e&7)*4 + klane.
// ---------------------------------------------------------------------------
__global__ void weff_kernel(const float* __restrict__ W1,
                            const float* __restrict__ b1,
                            const float* __restrict__ W2,
                            const float* __restrict__ b2)
{
    __shared__ float row[RED_];
    int c = blockIdx.x;
    int e = threadIdx.x;          // 0..143
    if (c < C_) {
        if (e < RED_) row[e] = W1[c * RED_ + e];
        __syncthreads();
        float acc = 0.f;
        #pragma unroll 8
        for (int d = 0; d < RED_; ++d)
            acc += row[d] * W2[d * E_ + e];
        int kstep = c >> 3, r = c & 7;
        int ntile = e >> 3;
        int lane  = ((e & 7) << 2) + (r & 3);
        g_weffB[(((kstep * 18 + ntile) * 32 + lane) << 1) + (r >> 2)] = acc;
    } else {
        if (e < RED_) row[e] = b1[e];
        __syncthreads();
        float acc = b2[e];
        #pragma unroll 8
        for (int d = 0; d < RED_; ++d)
            acc += row[d] * W2[d * E_ + e];
        g_beff[e] = acc;
    }
}

// ---------------------------------------------------------------------------
// tf32 split helpers + mma.sync
// ---------------------------------------------------------------------------
__device__ __forceinline__ void tf32_split(float v, uint32_t& hi, uint32_t& lo) {
    uint32_t u = __float_as_uint(v);
    hi = u & 0xffffe000u;                           // exact tf32 (top 19 bits)
    lo = __float_as_uint(v - __uint_as_float(hi));  // residual, |lo| <= 2^-11 |v|
}
__device__ __forceinline__ void mma_tf32(float* c, const uint32_t* a,
                                         uint32_t b0, uint32_t b1) {
    asm volatile(
        "mma.sync.aligned.m16n8k8.row.col.f32.tf32.tf32.f32 "
        "{%0,%1,%2,%3}, {%4,%5,%6,%7}, {%8,%9}, {%0,%1,%2,%3};"
        : "+f"(c[0]), "+f"(c[1]), "+f"(c[2]), "+f"(c[3])
        : "r"(a[0]), "r"(a[1]), "r"(a[2]), "r"(a[3]), "r"(b0), "r"(b1));
}
__device__ __forceinline__ uint32_t smem_u32(const void* p) {
    uint32_t a;
    asm("{ .reg .u64 t; cvta.to.shared.u64 t, %1; cvt.u32.u64 %0, t; }"
        : "=r"(a) : "l"(p));
    return a;
}
#define CP_ASYNC16(dst, src) \
    asm volatile("cp.async.cg.shared.global [%0], [%1], 16;" \
                 :: "r"(dst), "l"(src) : "memory")
#define CP_COMMIT() asm volatile("cp.async.commit_group;" ::: "memory")
#define CP_WAIT0()  asm volatile("cp.async.wait_group 0;" ::: "memory")

// ---------------------------------------------------------------------------
// Kernel 1: wgt = x @ Weff + beff via mma.sync tf32 (3-term split).
// Block 256 thr = 8 warps (4m x 2n). M-tile 128, N=144 full, K=256.
// B: whole matrix staged once in smem in fragment order (conflict-free LDS.64).
// A: 64-wide K chunks, cp.async double buffer, stride 68 (conflict-free LDS.32).
// ---------------------------------------------------------------------------
#define ASTRIDE 68
#define ABUF    (128 * ASTRIDE)              // 8704 floats
#define BFLOATS (32 * 18 * 32 * 2)           // 36864 floats
#define GEMM_SMEM ((BFLOATS + 2 * ABUF + 144) * 4)   // 217664 B

__global__ __launch_bounds__(256) void wgt_gemm_mma(const float* __restrict__ x)
{
    extern __shared__ float sm[];
    float* Bs = sm;                          // fragment-ordered B
    float* A0 = sm + BFLOATS;
    float* A1 = A0 + ABUF;
    float* bs = A1 + ABUF;                   // beff

    const int tid   = threadIdx.x;
    const int lane  = tid & 31;
    const int wid   = tid >> 5;
    const int warpM = (wid & 3) << 5;        // 0,32,64,96
    const int ntg0  = (wid >> 2) * 9;        // 0 or 9
    const int pm0   = blockIdx.x * 128;

    // stage B (coalesced float4)
    {
        const float4* src = reinterpret_cast<const float4*>(g_weffB);
        float4* dst = reinterpret_cast<float4*>(Bs);
        #pragma unroll
        for (int i = 0; i < 36; ++i)
            dst[tid + 256 * i] = src[tid + 256 * i];
    }
    if (tid < E_) bs[tid] = g_beff[tid];

    // A staging pattern: thread -> row am = tid>>1, half ah = tid&1, 8 float4
    const int am = tid >> 1;
    const int ah = tid & 1;
    const char* agp = reinterpret_cast<const char*>(
        x + (size_t)(pm0 + am) * C_ + ah * 32);
    const uint32_t as0 = smem_u32(A0) + (am * ASTRIDE + ah * 32) * 4;
    const uint32_t as1 = smem_u32(A1) + (am * ASTRIDE + ah * 32) * 4;

    // prologue: chunk 0 into A0
    #pragma unroll
    for (int j = 0; j < 8; ++j)
        CP_ASYNC16(as0 + j * 16, agp + j * 16);
    CP_COMMIT();

    float C[2][9][4];
    #pragma unroll
    for (int mt = 0; mt < 2; ++mt)
        #pragma unroll
        for (int nt = 0; nt < 9; ++nt)
            #pragma unroll
            for (int q = 0; q < 4; ++q) C[mt][nt][q] = 0.f;

    CP_WAIT0();
    __syncthreads();

    #pragma unroll 1
    for (int kc = 0; kc < 4; ++kc) {
        // prefetch next chunk into the other buffer (overlaps compute)
        if (kc < 3) {
            uint32_t dsts = (kc & 1) ? as0 : as1;
            const char* srcs = agp + (size_t)(kc + 1) * 256;  // 64 floats
            #pragma unroll
            for (int j = 0; j < 8; ++j)
                CP_ASYNC16(dsts + j * 16, srcs + j * 16);
            CP_COMMIT();
        }

        const float* Ab = (kc & 1) ? A1 : A0;
        // per-thread fragment base: row warpM + (lane>>2), col lane&3
        const float* at = Ab + (warpM + (lane >> 2)) * ASTRIDE + (lane & 3);
        const float2* bt = reinterpret_cast<const float2*>(Bs) +
                           (kc * 8 * 18 + ntg0) * 32 + lane;

        #pragma unroll 2
        for (int ks = 0; ks < 8; ++ks) {
            // A fragments (hi/lo) for 2 m-tiles
            uint32_t ahf[2][4], alf[2][4];
            #pragma unroll
            for (int mt = 0; mt < 2; ++mt) {
                const float* p = at + mt * (16 * ASTRIDE) + ks * 8;
                tf32_split(p[0],               ahf[mt][0], alf[mt][0]);
                tf32_split(p[8 * ASTRIDE],     ahf[mt][1], alf[mt][1]);
                tf32_split(p[4],               ahf[mt][2], alf[mt][2]);
                tf32_split(p[8 * ASTRIDE + 4], ahf[mt][3], alf[mt][3]);
            }
            // B fragments (hi/lo) for 9 n-tiles
            uint32_t bh[9][2], bl[9][2];
            #pragma unroll
            for (int nt = 0; nt < 9; ++nt) {
                float2 v = bt[(ks * 18 + nt) * 32];
                tf32_split(v.x, bh[nt][0], bl[nt][0]);
                tf32_split(v.y, bh[nt][1], bl[nt][1]);
            }
            // 3-term MMAs
            #pragma unroll
            for (int mt = 0; mt < 2; ++mt)
                #pragma unroll
                for (int nt = 0; nt < 9; ++nt) {
                    mma_tf32(C[mt][nt], ahf[mt], bh[nt][0], bh[nt][1]);
                    mma_tf32(C[mt][nt], ahf[mt], bl[nt][0], bl[nt][1]);
                    mma_tf32(C[mt][nt], alf[mt], bh[nt][0], bh[nt][1]);
                }
        }
        CP_WAIT0();
        __syncthreads();
    }

    // Epilogue: C + beff -> g_wgt (float2 stores)
    #pragma unroll
    for (int mt = 0; mt < 2; ++mt) {
        int r   = pm0 + warpM + mt * 16 + (lane >> 2);
        #pragma unroll
        for (int nt = 0; nt < 9; ++nt) {
            int col = (ntg0 + nt) * 8 + (lane & 3) * 2;
            float bx = bs[col], by = bs[col + 1];
            float2 v0 = make_float2(C[mt][nt][0] + bx, C[mt][nt][1] + by);
            float2 v1 = make_float2(C[mt][nt][2] + bx, C[mt][nt][3] + by);
            *reinterpret_cast<float2*>(g_wgt + (size_t)r * E_ + col)       = v0;
            *reinterpret_cast<float2*>(g_wgt + (size_t)(r + 8) * E_ + col) = v1;
        }
    }
}

// ---------------------------------------------------------------------------
// Kernel 2: involution apply (unchanged; conflict-free LDS, warp-per-pixel).
// ---------------------------------------------------------------------------
__global__ __launch_bounds__(256) void invo_kernel(const float* __restrict__ x,
                                                   float* __restrict__ out)
{
    __shared__ float xs[3][10][C_];
    __shared__ float wgts[8][E_];
    __shared__ unsigned short T[KK_][256];

    const int tid = threadIdx.x;
    const int w0  = blockIdx.x * 8;
    const int h   = blockIdx.y;
    const int b   = blockIdx.z;

    #pragma unroll
    for (int it = 0; it < 30; ++it) {
        int r  = it / 10;
        int cc = it - r * 10;
        int hh = h - 1 + r;
        int ww = w0 - 1 + cc;
        float v = 0.f;
        if (hh >= 0 && hh < H_ && ww >= 0 && ww < W_)
            v = x[(((size_t)b * H_ + hh) * W_ + ww) * C_ + tid];
        xs[r][cc][tid] = v;
    }

    const int p0 = (b * H_ + h) * W_ + w0;
    #pragma unroll
    for (int it = 0; it < 5; ++it) {
        int idx = tid + it * 256;
        if (idx < 8 * E_) {
            int pp = idx / E_;
            int e  = idx - pp * E_;
            wgts[pp][e] = g_wgt[(size_t)(p0 + pp) * E_ + e];
        }
    }

    {
        int o   = tid;
        int g   = o >> 4;
        int gc2 = o & 15;
        int fb  = g * 144 + gc2 * 9;
        #pragma unroll
        for (int kp = 0; kp < KK_; ++kp) {
            int f  = fb + kp;
            int chn = f & 255;
            int k  = f >> 8;
            int di = k / 3;
            int dj = k - di * 3;
            T[kp][o] = (unsigned short)(((di * 10 + dj) << 8) + chn);
        }
    }
    __syncthreads();

    const int p = tid >> 5;
    const int l = tid & 31;
    const float* xsp  = &xs[0][0][0] + p * C_;
    const float* wrow = &wgts[p][0];

    float acc[8];
    #pragma unroll
    for (int i = 0; i < 8; ++i) {
        int o = (i << 5) + l;
        int g = o >> 4;
        const int wb = g * 9;
        float a = 0.f;
        #pragma unroll
        for (int kp = 0; kp < KK_; ++kp) {
            int t = T[kp][o];
            a += wrow[wb + kp] * xsp[t];
        }
        acc[i] = a;
    }

    float* op = out + (size_t)(p0 + p) * C_ + l;
    #pragma unroll
    for (int i = 0; i < 8; ++i) op[i * 32] = acc[i];
}

// ---------------------------------------------------------------------------
extern "C" void kernel_launch(void* const* d_in, const int* in_sizes, int n_in,
                              void* d_out, int out_size)
{
    const float* x  = (const float*)d_in[0];
    const float* W1 = (const float*)d_in[1];
    const float* b1 = (const float*)d_in[2];
    const float* W2 = (const float*)d_in[3];
    const float* b2 = (const float*)d_in[4];
    float* out = (float*)d_out;

    cudaFuncSetAttribute(wgt_gemm_mma,
                         cudaFuncAttributeMaxDynamicSharedMemorySize, GEMM_SMEM);

    weff_kernel<<<257, 144>>>(W1, b1, W2, b2);
    wgt_gemm_mma<<<NPIX / 128, 256, GEMM_SMEM>>>(x);
    invo_kernel<<<dim3(W_ / 8, H_, B_), 256>>>(x, out);
}